// round 2
// baseline (speedup 1.0000x reference)
#include <cuda_runtime.h>
#include <cstdint>

typedef unsigned long long u64;

// ---------------- scratch (static device memory; no allocs allowed) ----------------
__device__ __align__(16) float g_bufA[128 * 256 * 512];   // 67 MB  (layer0 out, even layers)
__device__ __align__(16) float g_bufB[128 * 256 * 256];   // 33.5 MB (odd layers)
__device__ __align__(16) float g_part[128 * 256 * 64];    // 8.4 MB split-K partials

// ---------------- f32x2 packed math helpers ----------------
__device__ __forceinline__ u64 dup2(float x) {
    u64 r; unsigned xi = __float_as_uint(x);
    asm("mov.b64 %0, {%1, %2};" : "=l"(r) : "r"(xi), "r"(xi));
    return r;
}
__device__ __forceinline__ void fma2(u64& d, u64 a, u64 b) {
    asm("fma.rn.f32x2 %0, %1, %2, %0;" : "+l"(d) : "l"(a), "l"(b));
}

// ---------------- layer 0: (B,3,1024) x w0(256,3,512,2) -> act(512,256,128) ----------------
// act layout throughout: (p, c, b) : act[((p*256)+c)*128 + b]
__global__ void layer0_kernel(const float* __restrict__ x, const float* __restrict__ w0,
                              float* __restrict__ out)
{
    __shared__ float xs[6][128];            // [c*2+k][b]
    const int d   = blockIdx.x;             // 0..511
    const int tid = threadIdx.x;            // 256 threads
#pragma unroll
    for (int i = 0; i < 3; i++) {
        int e = tid + i * 256;               // 0..767
        int ck = e >> 7, b = e & 127;
        int c = ck >> 1, k = ck & 1;
        xs[ck][b] = x[(b * 3 + c) * 1024 + 2 * d + k];
    }
    __syncthreads();
    const int b  = tid & 127;
    const int oh = tid >> 7;
    const float2* w2 = (const float2*)w0;    // w0[((o*3+c)*512+d)*2+k]
    for (int o = oh; o < 256; o += 2) {
        float acc = 0.f;
#pragma unroll
        for (int c = 0; c < 3; c++) {
            float2 wv = w2[(o * 3 + c) * 512 + d];
            acc += xs[c * 2 + 0][b] * wv.x + xs[c * 2 + 1][b] * wv.y;
        }
        out[((size_t)d * 256 + o) * 128 + b] = fmaxf(acc * 0.5773502691896258f, 0.f);
    }
}

// ---------------- layers 1..9: per-position GEMM 128x128x(K slice), fp32 FFMA2 ----------------
// in : (p, c, b) with C=256, B=128
// w  : (o=256, c=256, dl, k=2)
// out: fused  -> act (d, o, b), relu(scale*sum)
//      partial-> g_part[(s*dl + d)*32768 + o*128 + b] raw sums
#define KC 16   // K values per stage = 8 channels x 2 taps

__global__ __launch_bounds__(256, 2)
void lc_gemm(const float* __restrict__ in, const float* __restrict__ w,
             float* __restrict__ out, int dl, int nchunks, float scale, int partial)
{
    __shared__ __align__(16) float As[2][KC][128];
    __shared__ __align__(16) float Ws[2][KC][128];

    const int tid = threadIdx.x;
    const int oh  = blockIdx.x;                 // 0/1 -> o base 0/128
    const int d   = blockIdx.y;
    const int s   = blockIdx.z;                 // split-K slice
    const int c0b = s * nchunks * 8;

    const int lr = tid >> 4;                    // 0..15 : A load row / compute b-group
    const int lj = tid & 15;                    // 0..15 : A load col / compute o-group
    const int trow = lr, tcol = lj;
    const int wo  = tid & 127;                  // weight-load o
    const int wch = tid >> 7;                   // weight-load channel half

    const float*  inp = in + (size_t)(2 * d) * (256 * 128);
    const float2* w2  = (const float2*)w;
    const size_t  wbase = (size_t)(oh * 128 + wo) * 256;

    u64 acc[8][4];
#pragma unroll
    for (int i = 0; i < 8; i++)
#pragma unroll
        for (int j = 0; j < 4; j++) acc[i][j] = 0ull;

    // ---- prologue: stage 0 ----
    {
        const int c0 = c0b;
        const int cl = lr >> 1, k = lr & 1;
        const float4* srcA = (const float4*)(inp + (size_t)k * (256 * 128) + (size_t)(c0 + cl) * 128);
        float4 a0 = srcA[lj];
        float4 a1 = srcA[lj + 16];
        *(float4*)&As[0][lr][lj * 4]      = a0;
        *(float4*)&As[0][lr][64 + lj * 4] = a1;
#pragma unroll
        for (int cc = 0; cc < 4; cc++) {
            const int cl2 = cc * 2 + wch;
            float2 v = w2[(wbase + (size_t)(c0 + cl2)) * dl + d];
            Ws[0][cl2 * 2 + 0][wo] = v.x;
            Ws[0][cl2 * 2 + 1][wo] = v.y;
        }
    }
    __syncthreads();

    const uint32_t ws_thread =
        (uint32_t)__cvta_generic_to_shared(&Ws[0][0][0]) + tcol * 16;

    int buf = 0;
    for (int ch = 0; ch < nchunks; ch++) {
        float4 nA0, nA1; float2 nW0, nW1, nW2, nW3;
        const bool more = (ch + 1 < nchunks);
        if (more) {
            const int c0 = c0b + (ch + 1) * 8;
            const int cl = lr >> 1, k = lr & 1;
            const float4* srcA = (const float4*)(inp + (size_t)k * (256 * 128) + (size_t)(c0 + cl) * 128);
            nA0 = srcA[lj];
            nA1 = srcA[lj + 16];
            nW0 = w2[(wbase + (size_t)(c0 + 0 * 2 + wch)) * dl + d];
            nW1 = w2[(wbase + (size_t)(c0 + 1 * 2 + wch)) * dl + d];
            nW2 = w2[(wbase + (size_t)(c0 + 2 * 2 + wch)) * dl + d];
            nW3 = w2[(wbase + (size_t)(c0 + 3 * 2 + wch)) * dl + d];
        }

#pragma unroll
        for (int kk = 0; kk < KC; kk++) {
            float a[8];
            *(float4*)&a[0] = *(const float4*)&As[buf][kk][4 * trow];
            *(float4*)&a[4] = *(const float4*)&As[buf][kk][64 + 4 * trow];
            u64 bp0, bp1, bp2, bp3;
            uint32_t wa = ws_thread + (uint32_t)(buf * KC + kk) * (128 * 4);
            asm volatile("ld.shared.v2.b64 {%0,%1}, [%2];" : "=l"(bp0), "=l"(bp1) : "r"(wa));
            asm volatile("ld.shared.v2.b64 {%0,%1}, [%2];" : "=l"(bp2), "=l"(bp3) : "r"(wa + 256));
#pragma unroll
            for (int i = 0; i < 8; i++) {
                u64 ad = dup2(a[i]);
                fma2(acc[i][0], ad, bp0);
                fma2(acc[i][1], ad, bp1);
                fma2(acc[i][2], ad, bp2);
                fma2(acc[i][3], ad, bp3);
            }
        }

        if (more) {
            const int nb = buf ^ 1;
            *(float4*)&As[nb][lr][lj * 4]      = nA0;
            *(float4*)&As[nb][lr][64 + lj * 4] = nA1;
            Ws[nb][(0 * 2 + wch) * 2 + 0][wo] = nW0.x;  Ws[nb][(0 * 2 + wch) * 2 + 1][wo] = nW0.y;
            Ws[nb][(1 * 2 + wch) * 2 + 0][wo] = nW1.x;  Ws[nb][(1 * 2 + wch) * 2 + 1][wo] = nW1.y;
            Ws[nb][(2 * 2 + wch) * 2 + 0][wo] = nW2.x;  Ws[nb][(2 * 2 + wch) * 2 + 1][wo] = nW2.y;
            Ws[nb][(3 * 2 + wch) * 2 + 0][wo] = nW3.x;  Ws[nb][(3 * 2 + wch) * 2 + 1][wo] = nW3.y;
        }
        __syncthreads();
        buf ^= 1;
    }

    // ---- epilogue ----
    size_t base = partial ? ((size_t)s * dl + d) * 32768 : (size_t)d * 32768;
    float* op = out + base;
#pragma unroll
    for (int i = 0; i < 8; i++) {
        const int b = (i < 4) ? (4 * trow + i) : (64 + 4 * trow + i - 4);
#pragma unroll
        for (int j = 0; j < 4; j++) {
            const int o0 = (j < 2) ? (4 * tcol + 2 * j) : (64 + 4 * tcol + 2 * (j - 2));
            const int o  = oh * 128 + o0;
            float lo, hi;
            asm("mov.b64 {%0,%1}, %2;" : "=f"(lo), "=f"(hi) : "l"(acc[i][j]));
            if (partial) {
                op[(size_t)o * 128 + b]       = lo;
                op[(size_t)(o + 1) * 128 + b] = hi;
            } else {
                op[(size_t)o * 128 + b]       = fmaxf(lo * scale, 0.f);
                op[(size_t)(o + 1) * 128 + b] = fmaxf(hi * scale, 0.f);
            }
        }
    }
}

// ---------------- split-K reduce + relu ----------------
__global__ void reduce_relu_kernel(const float* __restrict__ part, float* __restrict__ out,
                                   int n, int S, float scale)
{
    int idx = blockIdx.x * 256 + threadIdx.x;
    if (idx >= n) return;
    float s = 0.f;
    for (int i = 0; i < S; i++) s += part[(size_t)i * n + idx];
    out[idx] = fmaxf(s * scale, 0.f);
}

// ---------------- head: out[b,t] = (1/256) * sum_o act9[o,b] * beta[o,t] ----------------
__global__ void head_kernel(const float* __restrict__ act, const float* __restrict__ beta,
                            float* __restrict__ out)
{
    const int t = blockIdx.x;     // 0..9
    const int b = threadIdx.x;    // 0..127
    float s = 0.f;
#pragma unroll 8
    for (int o = 0; o < 256; o++)
        s += act[o * 128 + b] * __ldg(&beta[o * 10 + t]);
    out[b * 10 + t] = s * (1.0f / 256.0f);
}

// ---------------- launch ----------------
extern "C" void kernel_launch(void* const* d_in, const int* in_sizes, int n_in,
                              void* d_out, int out_size)
{
    const float* x = (const float*)d_in[0];
    const float* wl[10];
    for (int l = 0; l < 10; l++) wl[l] = (const float*)d_in[1 + l];
    const float* beta = (const float*)d_in[11];
    float* out = (float*)d_out;

    float *bufA, *bufB, *part;
    cudaGetSymbolAddress((void**)&bufA, g_bufA);
    cudaGetSymbolAddress((void**)&bufB, g_bufB);
    cudaGetSymbolAddress((void**)&part, g_part);

    layer0_kernel<<<512, 256>>>(x, wl[0], bufA);

    float* cur = bufA;
    float* nxt = bufB;
    int dl = 256;
    for (int l = 1; l <= 9; l++) {
        int S;
        if (dl >= 64)      S = 1;
        else if (dl == 32) S = 2;
        else if (dl == 16) S = 4;
        else if (dl == 8)  S = 8;
        else if (dl == 4)  S = 16;
        else               S = 32;
        const int nch = 32 / S;
        if (S == 1) {
            lc_gemm<<<dim3(2, dl, 1), 256>>>(cur, wl[l], nxt, dl, nch, 0.0625f, 0);
        } else {
            lc_gemm<<<dim3(2, dl, S), 256>>>(cur, wl[l], part, dl, nch, 0.0625f, 1);
            const int n = dl * 32768;
            reduce_relu_kernel<<<(n + 255) / 256, 256>>>(part, nxt, n, S, 0.0625f);
        }
        float* tmp = cur; cur = nxt; nxt = tmp;
        dl >>= 1;
    }

    head_kernel<<<10, 128>>>(cur, beta, out);
}

// round 4
// speedup vs baseline: 1.2213x; 1.2213x over previous
#include <cuda_runtime.h>
#include <cuda_bf16.h>
#include <cstdint>

typedef unsigned long long u64;

// ---------------- static scratch ----------------
// activations layout: (p, b, c) : act[(p*128 + b)*256 + c]
__device__ __align__(16) float g_bufA[512 * 128 * 256];   // 67 MB
__device__ __align__(16) float g_bufB[256 * 128 * 256];   // 33.5 MB
__device__ __align__(16) float g_part[4194304];           // 16.8 MB split-K partials

// ---------------- helpers ----------------
__device__ __forceinline__ uint32_t s2u(const void* p) {
    uint32_t a;
    asm("{\n\t.reg .u64 t;\n\tcvta.to.shared.u64 t, %1;\n\tcvt.u32.u64 %0, t;\n\t}" : "=r"(a) : "l"(p));
    return a;
}
// pack: first arg -> low bf16 half, second -> high half
__device__ __forceinline__ uint32_t packbf(float lo, float hi) {
    uint32_t r;
    asm("cvt.rn.bf16x2.f32 %0, %1, %2;" : "=r"(r) : "f"(hi), "f"(lo));
    return r;
}
__device__ __forceinline__ void split2(float x0, float x1, uint32_t& hi, uint32_t& lo) {
    uint32_t h = packbf(x0, x1);
    __nv_bfloat162 h2 = *(__nv_bfloat162*)&h;
    float r0 = x0 - __bfloat162float(h2.x);
    float r1 = x1 - __bfloat162float(h2.y);
    lo = packbf(r0, r1);
    hi = h;
}
__device__ __forceinline__ void ldsm4(uint32_t* r, uint32_t addr) {
    asm volatile("ldmatrix.sync.aligned.m8n8.x4.shared.b16 {%0,%1,%2,%3}, [%4];"
        : "=r"(r[0]), "=r"(r[1]), "=r"(r[2]), "=r"(r[3]) : "r"(addr));
}
__device__ __forceinline__ void mma16816(float* d, const uint32_t* a, uint32_t b0, uint32_t b1) {
    asm volatile("mma.sync.aligned.m16n8k16.row.col.f32.bf16.bf16.f32 "
        "{%0,%1,%2,%3}, {%4,%5,%6,%7}, {%8,%9}, {%0,%1,%2,%3};"
        : "+f"(d[0]), "+f"(d[1]), "+f"(d[2]), "+f"(d[3])
        : "r"(a[0]), "r"(a[1]), "r"(a[2]), "r"(a[3]), "r"(b0), "r"(b1));
}

// ---------------- layer 0 ----------------
__global__ void layer0_kernel(const float* __restrict__ x, const float* __restrict__ w0,
                              float* __restrict__ out)
{
    __shared__ float xs[6][128];
    const int d   = blockIdx.x;
    const int tid = threadIdx.x;
#pragma unroll
    for (int i = 0; i < 3; i++) {
        int e = tid + i * 256;
        int ck = e >> 7, b = e & 127;
        int c = ck >> 1, k = ck & 1;
        xs[ck][b] = x[(b * 3 + c) * 1024 + 2 * d + k];
    }
    __syncthreads();
    const int b  = tid & 127;
    const int oh = tid >> 7;
    const float2* w2 = (const float2*)w0;
    for (int o = oh; o < 256; o += 2) {
        float acc = 0.f;
#pragma unroll
        for (int c = 0; c < 3; c++) {
            float2 wv = w2[(o * 3 + c) * 512 + d];
            acc += xs[c * 2 + 0][b] * wv.x + xs[c * 2 + 1][b] * wv.y;
        }
        out[((size_t)d * 128 + b) * 256 + o] = fmaxf(acc * 0.5773502691896258f, 0.f);
    }
}

// ---------------- layers 1..9: warp-mma bf16x3 GEMM ----------------
// in : (p, b, c)  C=256, B=128 ; w : (256, 256, dl, 2)
// CTA: M=128(b) x N=128(o half) x K-slice (nst*32), kappa = 2c+k
// smem tiles: 128 rows x 128B (hi chunks 0-3 = kappa 0..31, lo chunks 4-7), SW128 swizzle
#define SMEM_BYTES 65536

__global__ __launch_bounds__(256, 1)
void lc_mma(const float* __restrict__ in, const float* __restrict__ w,
            float* __restrict__ out, int dl, int nst, float scale, int partial)
{
    extern __shared__ __align__(1024) char smem[];
    const uint32_t sb = s2u(smem);
    const int tid  = threadIdx.x;
    const int wid  = tid >> 5, lane = tid & 31;
    const int oh   = blockIdx.x;
    const int d    = blockIdx.y;
    const int s    = blockIdx.z;
    const int cbase = s * nst * 16;

    // ---- loader roles ----
    const int r  = tid >> 1;          // row: b for A, o_local for B
    const int h  = tid & 1;           // channel half (8 channels)
    const float*  a0p = in + ((size_t)(2 * d) * 128 + r) * 256;
    const float*  a1p = a0p + 128 * 256;
    const float2* w2  = (const float2*)w;
    const size_t  wrow = (size_t)(oh * 128 + r) * 256;

    // swizzled store offsets (constant across stages)
    const uint32_t rowb = (uint32_t)r * 128, xs_ = (uint32_t)(r & 7) << 4;
    const uint32_t offH0 = rowb + (((uint32_t)(2 * h) * 16) ^ xs_);
    const uint32_t offH1 = rowb + (((uint32_t)(2 * h + 1) * 16) ^ xs_);
    const uint32_t offL0 = rowb + (((uint32_t)(4 + 2 * h) * 16) ^ xs_);
    const uint32_t offL1 = rowb + (((uint32_t)(5 + 2 * h) * 16) ^ xs_);

    // buffer bases: A0, B0, A1, B1
    const uint32_t AB[2] = { sb, sb + 32768 };

    // ---- compute roles ----
    const int mh = wid & 1, nq = wid >> 1;
    const uint32_t co = (uint32_t)(lane >> 4) * 16;
    const uint32_t xa = (uint32_t)(lane & 7) << 4;
    uint32_t rA[4], rB[2];
#pragma unroll
    for (int mi = 0; mi < 4; mi++) rA[mi] = (uint32_t)(mh * 64 + mi * 16 + (lane & 15)) * 128;
#pragma unroll
    for (int bj = 0; bj < 2; bj++) rB[bj] = (uint32_t)(nq * 32 + bj * 16 + (lane & 15)) * 128;

    float D[4][4][4];
#pragma unroll
    for (int i = 0; i < 4; i++)
#pragma unroll
        for (int j = 0; j < 4; j++)
#pragma unroll
            for (int q = 0; q < 4; q++) D[i][j][q] = 0.f;

    float  fa[16];   // raw A (8 from each position)
    float2 fb[8];    // raw B

    auto issue_loads = [&](int t) {
        const int c0 = cbase + t * 16 + 8 * h;
        *(float4*)&fa[0]  = *(const float4*)(a0p + c0);
        *(float4*)&fa[4]  = *(const float4*)(a0p + c0 + 4);
        *(float4*)&fa[8]  = *(const float4*)(a1p + c0);
        *(float4*)&fa[12] = *(const float4*)(a1p + c0 + 4);
#pragma unroll
        for (int j = 0; j < 8; j++)
            fb[j] = w2[(wrow + (size_t)(c0 + j)) * dl + d];
    };

    auto convert_store = [&](int buf) {
        uint32_t Ah[8], Al[8], Bh[8], Bl[8];
#pragma unroll
        for (int j = 0; j < 8; j++) {
            split2(fa[j], fa[8 + j], Ah[j], Al[j]);
            split2(fb[j].x, fb[j].y, Bh[j], Bl[j]);
        }
        const uint32_t ab = AB[buf], bb = AB[buf] + 16384;
        asm volatile("st.shared.v4.b32 [%0], {%1,%2,%3,%4};" :: "r"(ab + offH0), "r"(Ah[0]), "r"(Ah[1]), "r"(Ah[2]), "r"(Ah[3]));
        asm volatile("st.shared.v4.b32 [%0], {%1,%2,%3,%4};" :: "r"(ab + offH1), "r"(Ah[4]), "r"(Ah[5]), "r"(Ah[6]), "r"(Ah[7]));
        asm volatile("st.shared.v4.b32 [%0], {%1,%2,%3,%4};" :: "r"(ab + offL0), "r"(Al[0]), "r"(Al[1]), "r"(Al[2]), "r"(Al[3]));
        asm volatile("st.shared.v4.b32 [%0], {%1,%2,%3,%4};" :: "r"(ab + offL1), "r"(Al[4]), "r"(Al[5]), "r"(Al[6]), "r"(Al[7]));
        asm volatile("st.shared.v4.b32 [%0], {%1,%2,%3,%4};" :: "r"(bb + offH0), "r"(Bh[0]), "r"(Bh[1]), "r"(Bh[2]), "r"(Bh[3]));
        asm volatile("st.shared.v4.b32 [%0], {%1,%2,%3,%4};" :: "r"(bb + offH1), "r"(Bh[4]), "r"(Bh[5]), "r"(Bh[6]), "r"(Bh[7]));
        asm volatile("st.shared.v4.b32 [%0], {%1,%2,%3,%4};" :: "r"(bb + offL0), "r"(Bl[0]), "r"(Bl[1]), "r"(Bl[2]), "r"(Bl[3]));
        asm volatile("st.shared.v4.b32 [%0], {%1,%2,%3,%4};" :: "r"(bb + offL1), "r"(Bl[4]), "r"(Bl[5]), "r"(Bl[6]), "r"(Bl[7]));
    };

    issue_loads(0);
    convert_store(0);
    __syncthreads();

    for (int t = 0; t < nst; t++) {
        const int buf = t & 1;
        if (t + 1 < nst) issue_loads(t + 1);

        const uint32_t ab = AB[buf], bb = AB[buf] + 16384;
#pragma unroll
        for (int kk = 0; kk < 2; kk++) {
            uint32_t Ahf[4][4], Alf[4][4], Bhf[2][4], Blf[2][4];
            const uint32_t khi = (uint32_t)(32 * kk) + co;
            const uint32_t klo = khi + 64;
#pragma unroll
            for (int mi = 0; mi < 4; mi++) {
                ldsm4(Ahf[mi], ab + rA[mi] + (khi ^ xa));
                ldsm4(Alf[mi], ab + rA[mi] + (klo ^ xa));
            }
#pragma unroll
            for (int bj = 0; bj < 2; bj++) {
                ldsm4(Bhf[bj], bb + rB[bj] + (khi ^ xa));
                ldsm4(Blf[bj], bb + rB[bj] + (klo ^ xa));
            }
#pragma unroll
            for (int mi = 0; mi < 4; mi++) {
#pragma unroll
                for (int nj = 0; nj < 4; nj++) {
                    const int bt = nj >> 1, bs = nj & 1;
                    mma16816(D[mi][nj], Ahf[mi], Bhf[bt][bs], Bhf[bt][bs + 2]);
                    mma16816(D[mi][nj], Alf[mi], Bhf[bt][bs], Bhf[bt][bs + 2]);
                    mma16816(D[mi][nj], Ahf[mi], Blf[bt][bs], Blf[bt][bs + 2]);
                }
            }
        }

        if (t + 1 < nst) convert_store(buf ^ 1);
        __syncthreads();
    }

    // ---- epilogue ----
    const int colq = nq * 32 + 2 * (lane & 3);
    if (partial) {
        float* pp = g_part + ((size_t)(s * 2 + oh) * dl + d) * 16384;
#pragma unroll
        for (int mi = 0; mi < 4; mi++) {
            const int b0 = mh * 64 + mi * 16 + (lane >> 2);
#pragma unroll
            for (int nj = 0; nj < 4; nj++) {
                const int col = colq + nj * 8;
                *(float2*)(pp + (size_t)b0 * 128 + col)       = make_float2(D[mi][nj][0], D[mi][nj][1]);
                *(float2*)(pp + (size_t)(b0 + 8) * 128 + col) = make_float2(D[mi][nj][2], D[mi][nj][3]);
            }
        }
    } else {
        float* op = out + (size_t)d * 128 * 256 + oh * 128;
#pragma unroll
        for (int mi = 0; mi < 4; mi++) {
            const int b0 = mh * 64 + mi * 16 + (lane >> 2);
#pragma unroll
            for (int nj = 0; nj < 4; nj++) {
                const int col = colq + nj * 8;
                float2 v0 = make_float2(fmaxf(D[mi][nj][0] * scale, 0.f), fmaxf(D[mi][nj][1] * scale, 0.f));
                float2 v1 = make_float2(fmaxf(D[mi][nj][2] * scale, 0.f), fmaxf(D[mi][nj][3] * scale, 0.f));
                *(float2*)(op + (size_t)b0 * 256 + col)       = v0;
                *(float2*)(op + (size_t)(b0 + 8) * 256 + col) = v1;
            }
        }
    }
}

// ---------------- split-K reduce + relu ----------------
__global__ void reduce_relu_kernel(const float* __restrict__ part, float* __restrict__ out,
                                   int n, int dl, int S, float scale)
{
    int idx = blockIdx.x * 256 + threadIdx.x;
    if (idx >= n) return;
    const int o  = idx & 255;
    const int b  = (idx >> 8) & 127;
    const int dd = idx >> 15;
    const int ohh = o >> 7, ol = o & 127;
    float sum = 0.f;
    for (int si = 0; si < S; si++)
        sum += part[((size_t)(si * 2 + ohh) * dl + dd) * 16384 + b * 128 + ol];
    out[idx] = fmaxf(sum * scale, 0.f);
}

// ---------------- head ----------------
__global__ void head_kernel(const float* __restrict__ act, const float* __restrict__ beta,
                            float* __restrict__ out)
{
    const int t = blockIdx.x;
    const int b = threadIdx.x;
    float s = 0.f;
#pragma unroll 8
    for (int o = 0; o < 256; o++)
        s += act[b * 256 + o] * __ldg(&beta[o * 10 + t]);
    out[b * 10 + t] = s * (1.0f / 256.0f);
}

// ---------------- launch ----------------
extern "C" void kernel_launch(void* const* d_in, const int* in_sizes, int n_in,
                              void* d_out, int out_size)
{
    const float* x = (const float*)d_in[0];
    const float* wl[10];
    for (int l = 0; l < 10; l++) wl[l] = (const float*)d_in[1 + l];
    const float* beta = (const float*)d_in[11];
    float* out = (float*)d_out;

    float *bufA, *bufB, *part;
    cudaGetSymbolAddress((void**)&bufA, g_bufA);
    cudaGetSymbolAddress((void**)&bufB, g_bufB);
    cudaGetSymbolAddress((void**)&part, g_part);

    static int smem_set = 0;
    if (!smem_set) {
        cudaFuncSetAttribute(lc_mma, cudaFuncAttributeMaxDynamicSharedMemorySize, SMEM_BYTES);
        smem_set = 1;
    }

    layer0_kernel<<<512, 256>>>(x, wl[0], bufA);

    float* cur = bufA;
    float* nxt = bufB;
    int dl = 256;
    const float scale = 0.0625f;
    for (int l = 1; l <= 9; l++) {
        int S;
        if (dl >= 128)     S = 1;
        else if (dl == 64) S = 2;
        else if (dl == 32) S = 4;
        else               S = 8;
        const int nst = 16 / S;
        if (S == 1) {
            lc_mma<<<dim3(2, dl, 1), 256, SMEM_BYTES>>>(cur, wl[l], nxt, dl, nst, scale, 0);
        } else {
            lc_mma<<<dim3(2, dl, S), 256, SMEM_BYTES>>>(cur, wl[l], part, dl, nst, scale, 1);
            const int n = dl * 32768;
            reduce_relu_kernel<<<(n + 255) / 256, 256>>>(part, nxt, n, dl, S, scale);
        }
        float* tmp = cur; cur = nxt; nxt = tmp;
        dl >>= 1;
    }

    head_kernel<<<10, 128>>>(cur, beta, out);
}